// round 11
// baseline (speedup 1.0000x reference)
#include <cuda_runtime.h>
#include <cuda_fp16.h>
#include <cstdint>

// LatticeCNN on GB300 — closed-form lattice conv decomposition, fp16 mma.sync,
// fp16-resident activations/weights. Structure = round-7 best (1 unit/block,
// sync staging, scalar fragment gathers); data path fp16 end-to-end between
// kernels to halve traffic, delete conversions, and double occupancy.
//
// join conv  == pointwise with 2-D prefix-summed weights
// meet conv  == pointwise(suffix weights) + x-prefix row strips + y-prefix col
//               strips + 2-D-prefix corner term

#define ALPHA  0.5f
#define SLOPE  0.01f
#define S      32
#define FOUT   128

__device__ __forceinline__ uint32_t pack_f16x2(float lo, float hi) {
    uint32_t r;
    asm("cvt.rn.f16x2.f32 %0, %1, %2;" : "=r"(r) : "f"(hi), "f"(lo));
    return r;
}

__device__ __forceinline__ void mma16(float (&d)[4], const uint4& a,
                                      uint32_t b0, uint32_t b1) {
    asm volatile(
        "mma.sync.aligned.m16n8k16.row.col.f32.f16.f16.f32 "
        "{%0,%1,%2,%3}, {%4,%5,%6,%7}, {%8,%9}, {%0,%1,%2,%3};"
        : "+f"(d[0]), "+f"(d[1]), "+f"(d[2]), "+f"(d[3])
        : "r"(a.x), "r"(a.y), "r"(a.z), "r"(a.w), "r"(b0), "r"(b1));
}

// ---------------- device scratch (no allocation allowed) ----------------
__device__ __half d_Xt0h[1024 * 64 * 64];    // layer0 input, pixel-major fp16
__device__ __half d_Yth [1024 * 64 * 128];   // layer0 out / layer1 in, fp16
__device__ float  d_Yt2 [1024 * 64 * 128];   // layer1 out (pixel-major, fp32)
__device__ __half d_WCT [225 * 128 * FOUT];  // pointwise weights [class][g][f]
__device__ __half d_MRST[64 * 128 * FOUT];   // row-suffix  [a*8+q][g][f]
__device__ __half d_MCST[64 * 128 * FOUT];   // col-suffix  [p*8+b][g][f]
__device__ __half d_MWT [64 * 128 * FOUT];   // raw meet    [a*8+b][g][f]
__device__ float  d_G   [224 * 64 * FOUT];   // row strip tiles  G[a][y]
__device__ float  d_CG  [224 * 64 * FOUT];   // col strip tiles  CG[b][x]
__device__ float  d_H   [49  * 64 * FOUT];   // corner tiles     H[a][b]

// ---------------- transposes ----------------
// dst[C][R] fp16 = src[R][C] fp32, vectorized 4B writes (2 halves / thread).
__global__ void transpose_h_k(__half* __restrict__ dst, const float* __restrict__ src,
                              int R, int C)
{
    __shared__ float tile[32][33];
    int c0 = blockIdx.x * 32, r0 = blockIdx.y * 32;
    #pragma unroll
    for (int i = 0; i < 4; i++)
        tile[threadIdx.y + 8 * i][threadIdx.x] =
            src[(size_t)(r0 + threadIdx.y + 8 * i) * C + c0 + threadIdx.x];
    __syncthreads();
    int tid = threadIdx.y * 32 + threadIdx.x;
    int rp = tid & 15, cc = tid >> 4;        // 16 row-pairs x 16 cols per pass
    #pragma unroll
    for (int pass = 0; pass < 2; pass++) {
        int c = cc + pass * 16;
        uint32_t v = pack_f16x2(tile[2 * rp][c], tile[2 * rp + 1][c]);
        *(uint32_t*)(dst + (size_t)(c0 + c) * R + r0 + 2 * rp) = v;
    }
}

__global__ void transpose_k(float* __restrict__ dst, const float* __restrict__ src,
                            int R, int C)
{
    __shared__ float tile[32][33];
    int c0 = blockIdx.x * 32, r0 = blockIdx.y * 32;
    #pragma unroll
    for (int i = 0; i < 4; i++)
        tile[threadIdx.y + 8 * i][threadIdx.x] =
            src[(size_t)(r0 + threadIdx.y + 8 * i) * C + c0 + threadIdx.x];
    __syncthreads();
    #pragma unroll
    for (int i = 0; i < 4; i++)
        dst[(size_t)(c0 + threadIdx.y + 8 * i) * R + r0 + threadIdx.x] =
            tile[threadIdx.x][threadIdx.y + 8 * i];
}

// ---------------- per-layer weight-table prep (fp16 [g][f] tables) ------
__global__ void prep_k(const float* __restrict__ mw, const float* __restrict__ jw,
                       __half* __restrict__ WCT, __half* __restrict__ MRST,
                       __half* __restrict__ MCST, __half* __restrict__ MWT, int Fin)
{
    int idx = blockIdx.x * blockDim.x + threadIdx.x;
    if (idx >= Fin * FOUT) return;
    int f = idx >> 7, g = idx & 127;
    int ss = Fin * FOUT;
    int src = f * FOUT + g;          // original [a][b][f][g]
    int tb  = g * Fin + f;           // transposed [g][f]

    float m[8][8];
    #pragma unroll
    for (int a = 0; a < 8; a++)
        #pragma unroll
        for (int b = 0; b < 8; b++) {
            m[a][b] = mw[(a * 8 + b) * ss + src];
            MWT[(a * 8 + b) * ss + tb] = __float2half_rn(m[a][b]);
        }

    {   // MCS[p][b] = sum_{a>=p} mw[a][b]
        float col[8];
        #pragma unroll
        for (int b = 0; b < 8; b++) col[b] = 0.f;
        #pragma unroll
        for (int p = 7; p >= 0; p--)
            #pragma unroll
            for (int b = 0; b < 8; b++) {
                col[b] += m[p][b];
                MCST[(p * 8 + b) * ss + tb] = __float2half_rn(col[b]);
            }
    }
    #pragma unroll
    for (int a = 0; a < 8; a++) {    // MRS[a][q] = sum_{b>=q}
        #pragma unroll
        for (int q = 6; q >= 0; q--) m[a][q] += m[a][q + 1];
        #pragma unroll
        for (int q = 0; q < 8; q++) MRST[(a * 8 + q) * ss + tb] = __float2half_rn(m[a][q]);
    }
    #pragma unroll
    for (int b = 0; b < 8; b++)      // -> 2-D suffix MS
        #pragma unroll
        for (int a = 6; a >= 0; a--) m[a][b] += m[a + 1][b];

    float j[8][8];
    #pragma unroll
    for (int a = 0; a < 8; a++)
        #pragma unroll
        for (int b = 0; b < 8; b++)
            j[a][b] = jw[(a * 8 + b) * ss + src];
    #pragma unroll
    for (int a = 0; a < 8; a++)
        #pragma unroll
        for (int b = 1; b < 8; b++) j[a][b] += j[a][b - 1];
    #pragma unroll
    for (int b = 0; b < 8; b++)
        #pragma unroll
        for (int a = 1; a < 8; a++) j[a][b] += j[a - 1][b];

    for (int cx = 0; cx < 15; cx++) {
        int ax = cx < 8 ? 0 : cx - 7;
        int jx = cx < 8 ? cx : 7;
        for (int cy = 0; cy < 15; cy++) {
            int ay = cy < 8 ? 0 : cy - 7;
            int jy = cy < 8 ? cy : 7;
            WCT[(cx * 15 + cy) * ss + tb] =
                __float2half_rn((1.0f - ALPHA) * m[ax][ay] + ALPHA * j[jx][jy]);
        }
    }
}

// ---------------- GEMM unit: [64 x FIN] * W^T[128 x FIN] -> acc regs -------
// 8 warps: warp (wm,wn) = (wid/4, wid%4) owns rows [wm*32,+32) x cols [wn*32,+32).
// smem: raw fp16 tiles, halfword stride LDh = FIN+8 (LDh/2 == 4 mod 32 ->
// every f16x2 fragment gather is a conflict-free LDS.32). Staging is plain
// 16B LDG -> 16B STS (data already fp16 in global).
template <int FIN>
__device__ __forceinline__ void unit_gemm(const __half* __restrict__ X,
                                          const __half* __restrict__ W,
                                          __half* sm, float (&acc)[2][4][4])
{
    constexpr int LDh = FIN + 8;
    constexpr int CR  = FIN / 8;     // 16B chunks per row
    __half* Xs = sm;                 // [64][LDh]
    __half* Ws = sm + 64 * LDh;      // [128][LDh]
    const int tid = threadIdx.x;

    #pragma unroll
    for (int c = tid; c < 64 * CR; c += 256) {
        int r = c / CR, k = (c % CR) * 8;
        *(uint4*)(Xs + r * LDh + k) = *(const uint4*)(X + r * FIN + k);
    }
    #pragma unroll
    for (int c = tid; c < 128 * CR; c += 256) {
        int r = c / CR, k = (c % CR) * 8;
        *(uint4*)(Ws + r * LDh + k) = *(const uint4*)(W + r * FIN + k);
    }
    __syncthreads();

    const int lane = tid & 31, wid = tid >> 5;
    const int wm = wid >> 2, wn = wid & 3;
    const __half* Ax = Xs + (wm * 32 + (lane >> 2)) * LDh + (lane & 3) * 2;
    const __half* Bx = Ws + (wn * 32 + (lane >> 2)) * LDh + (lane & 3) * 2;

    #pragma unroll
    for (int kt = 0; kt < FIN / 16; kt++) {
        const int k0 = kt * 16;
        uint4 a0, a1;
        a0.x = *(const uint32_t*)(Ax + k0);
        a0.y = *(const uint32_t*)(Ax + 8 * LDh + k0);
        a0.z = *(const uint32_t*)(Ax + k0 + 8);
        a0.w = *(const uint32_t*)(Ax + 8 * LDh + k0 + 8);
        a1.x = *(const uint32_t*)(Ax + 16 * LDh + k0);
        a1.y = *(const uint32_t*)(Ax + 24 * LDh + k0);
        a1.z = *(const uint32_t*)(Ax + 16 * LDh + k0 + 8);
        a1.w = *(const uint32_t*)(Ax + 24 * LDh + k0 + 8);
        uint32_t b[4][2];
        #pragma unroll
        for (int nt = 0; nt < 4; nt++) {
            b[nt][0] = *(const uint32_t*)(Bx + nt * 8 * LDh + k0);
            b[nt][1] = *(const uint32_t*)(Bx + nt * 8 * LDh + k0 + 8);
        }
        #pragma unroll
        for (int nt = 0; nt < 4; nt++) {
            mma16(acc[0][nt], a0, b[nt][0], b[nt][1]);
            mma16(acc[1][nt], a1, b[nt][0], b[nt][1]);
        }
    }
}

// ---------------- strips/corner: 497 units, 1 per block ----------------
template <int FIN>
__global__ void __launch_bounds__(256) strips_mc(
    const __half* __restrict__ Xt, const __half* __restrict__ MRST,
    const __half* __restrict__ MCST, const __half* __restrict__ MWT,
    float* __restrict__ G, float* __restrict__ CG, float* __restrict__ H)
{
    extern __shared__ __half smh[];
    int u = blockIdx.x;
    size_t ss = (size_t)FIN * FOUT;
    const __half* X; const __half* W; float* dst;
    if (u < 224) {
        int a = u >> 5, Y = u & 31;
        int q = Y > 24 ? Y - 24 : 0;
        X = Xt + (size_t)((a + 24) * S + Y) * 64 * FIN;
        W = MRST + (size_t)(a * 8 + q) * ss;
        dst = G + (size_t)u * 64 * FOUT;
    } else if (u < 448) {
        int t = u - 224;
        int b = t >> 5, Xc = t & 31;
        int p = Xc > 24 ? Xc - 24 : 0;
        X = Xt + (size_t)(Xc * S + b + 24) * 64 * FIN;
        W = MCST + (size_t)(p * 8 + b) * ss;
        dst = CG + (size_t)t * 64 * FOUT;
    } else {
        int t = u - 448;
        int a = t / 7, b = t % 7;
        X = Xt + (size_t)((a + 24) * S + b + 24) * 64 * FIN;
        W = MWT + (size_t)(a * 8 + b) * ss;
        dst = H + (size_t)t * 64 * FOUT;
    }

    float acc[2][4][4] = {};
    unit_gemm<FIN>(X, W, smh, acc);

    int lane = threadIdx.x & 31, wid = threadIdx.x >> 5;
    int wm = wid >> 2, wn = wid & 3;
    int r0 = wm * 32 + (lane >> 2);
    #pragma unroll
    for (int mt = 0; mt < 2; mt++)
        #pragma unroll
        for (int nt = 0; nt < 4; nt++) {
            int g = wn * 32 + nt * 8 + (lane & 3) * 2;
            int r = r0 + mt * 16;
            *(float2*)(dst + r * FOUT + g)       = make_float2(acc[mt][nt][0], acc[mt][nt][1]);
            *(float2*)(dst + (r + 8) * FOUT + g) = make_float2(acc[mt][nt][2], acc[mt][nt][3]);
        }
}

// ---------------- merged prefix pass: rows(G) + rows(CG) + 2-D(H) ----------
__global__ void prefix_all_k(float* __restrict__ G, float* __restrict__ CG,
                             float* __restrict__ H)
{
    int bid = blockIdx.x;
    if (bid < 2048) {
        int t = bid * 256 + threadIdx.x;
        float* buf = (t < 32 * 8192) ? G : CG;
        int tt = t & (32 * 8192 - 1);
        int yy = tt >> 13, mg = tt & 8191;
        float run = 0.f;
        #pragma unroll
        for (int a = 0; a < 7; a++) {
            int idx = (a * 32 + yy) * 8192 + mg;
            run += buf[idx];
            buf[idx] = run;
        }
    } else {
        int mg = (bid - 2048) * 256 + threadIdx.x;
        float colA[7];
        #pragma unroll
        for (int b = 0; b < 7; b++) colA[b] = 0.f;
        #pragma unroll
        for (int a = 0; a < 7; a++) {
            float run = 0.f;
            #pragma unroll
            for (int b = 0; b < 7; b++) {
                int idx = (a * 7 + b) * 8192 + mg;
                run += H[idx];
                colA[b] += run;
                H[idx] = colA[b];
            }
        }
    }
}

// ---------------- combine: 1024 pixels, 1 per block ----------------
template <int FIN, bool OUT_HALF>
__global__ void __launch_bounds__(256) combine_mc(
    const __half* __restrict__ Xt, const __half* __restrict__ WCT,
    const float* __restrict__ Gc, const float* __restrict__ CGc,
    const float* __restrict__ Hc, const float* __restrict__ mb,
    const float* __restrict__ jb, void* __restrict__ Yout)
{
    extern __shared__ __half smh[];
    int p = blockIdx.x;
    int X = p >> 5, Y = p & 31;
    int cx = X <= 24 ? (X < 7 ? X : 7) : X - 17;
    int cy = Y <= 24 ? (Y < 7 ? Y : 7) : Y - 17;
    size_t ss = (size_t)FIN * FOUT;

    float acc[2][4][4] = {};
    unit_gemm<FIN>(Xt + (size_t)p * 64 * FIN,
                   WCT + (size_t)(cx * 15 + cy) * ss, smh, acc);

    const float ms = 1.0f - ALPHA;
    const float* Gp = (X >= 25) ? Gc + (size_t)((X - 25) * S + Y) * 64 * FOUT : 0;
    const float* Cp = (Y >= 25) ? CGc + (size_t)((Y - 25) * S + X) * 64 * FOUT : 0;
    const float* Hp = (X >= 25 && Y >= 25)
        ? Hc + (size_t)((X - 25) * 7 + (Y - 25)) * 64 * FOUT : 0;

    int lane = threadIdx.x & 31, wid = threadIdx.x >> 5;
    int wm = wid >> 2, wn = wid & 3;
    int r0 = wm * 32 + (lane >> 2);

    #pragma unroll
    for (int nt = 0; nt < 4; nt++) {
        int g = wn * 32 + nt * 8 + (lane & 3) * 2;
        float2 bias = make_float2(ms * mb[g]     + ALPHA * jb[g],
                                  ms * mb[g + 1] + ALPHA * jb[g + 1]);
        #pragma unroll
        for (int mt = 0; mt < 2; mt++) {
            #pragma unroll
            for (int half = 0; half < 2; half++) {
                int r = r0 + mt * 16 + half * 8;
                float v0 = acc[mt][nt][half * 2], v1 = acc[mt][nt][half * 2 + 1];
                if (Gp) {
                    float2 s2 = *(const float2*)(Gp + r * FOUT + g);
                    v0 += ms * s2.x; v1 += ms * s2.y;
                }
                if (Cp) {
                    float2 s2 = *(const float2*)(Cp + r * FOUT + g);
                    v0 += ms * s2.x; v1 += ms * s2.y;
                }
                if (Hp) {
                    float2 s2 = *(const float2*)(Hp + r * FOUT + g);
                    v0 += ms * s2.x; v1 += ms * s2.y;
                }
                v0 += bias.x; v1 += bias.y;
                v0 = fmaxf(v0, SLOPE * v0);
                v1 = fmaxf(v1, SLOPE * v1);
                if (OUT_HALF) {
                    __half* O = (__half*)Yout + (size_t)p * 64 * FOUT;
                    *(uint32_t*)(O + r * FOUT + g) = pack_f16x2(v0, v1);
                } else {
                    float* O = (float*)Yout + (size_t)p * 64 * FOUT;
                    *(float2*)(O + r * FOUT + g) = make_float2(v0, v1);
                }
            }
        }
    }
}

// ---------------- host launch ----------------
extern "C" void kernel_launch(void* const* d_in, const int* in_sizes, int n_in,
                              void* d_out, int out_size)
{
    const float* x   = (const float*)d_in[0];
    const float* mw0 = (const float*)d_in[5];
    const float* mb0 = (const float*)d_in[6];
    const float* jw0 = (const float*)d_in[7];
    const float* jb0 = (const float*)d_in[8];
    const float* mw1 = (const float*)d_in[9];
    const float* mb1 = (const float*)d_in[10];
    const float* jw1 = (const float*)d_in[11];
    const float* jb1 = (const float*)d_in[12];
    float* out = (float*)d_out;

    __half *Xt0h, *Yth, *WCT, *MRST, *MCST, *MWT;
    float *Yt2, *G, *CG, *H;
    cudaGetSymbolAddress((void**)&Xt0h, d_Xt0h);
    cudaGetSymbolAddress((void**)&Yth,  d_Yth);
    cudaGetSymbolAddress((void**)&Yt2,  d_Yt2);
    cudaGetSymbolAddress((void**)&WCT,  d_WCT);
    cudaGetSymbolAddress((void**)&MRST, d_MRST);
    cudaGetSymbolAddress((void**)&MCST, d_MCST);
    cudaGetSymbolAddress((void**)&MWT,  d_MWT);
    cudaGetSymbolAddress((void**)&G,    d_G);
    cudaGetSymbolAddress((void**)&CG,   d_CG);
    cudaGetSymbolAddress((void**)&H,    d_H);

    const int smem64  = 192 * (64 + 8)  * 2;   // 27648 B -> 8 blocks/SM
    const int smem128 = 192 * (128 + 8) * 2;   // 52224 B -> 4 blocks/SM
    cudaFuncSetAttribute(strips_mc<64>,  cudaFuncAttributeMaxDynamicSharedMemorySize, smem64);
    cudaFuncSetAttribute(combine_mc<64, true>,
                         cudaFuncAttributeMaxDynamicSharedMemorySize, smem64);
    cudaFuncSetAttribute(strips_mc<128>, cudaFuncAttributeMaxDynamicSharedMemorySize, smem128);
    cudaFuncSetAttribute(combine_mc<128, false>,
                         cudaFuncAttributeMaxDynamicSharedMemorySize, smem128);

    dim3 tb(32, 8);
    // x [4096][1024] fp32 -> Xt0h [1024][4096] fp16
    transpose_h_k<<<dim3(1024 / 32, 4096 / 32), tb>>>(Xt0h, x, 4096, 1024);

    // ---- layer 0: Fin = 64 ----
    prep_k<<<(64 * 128) / 256, 256>>>(mw0, jw0, WCT, MRST, MCST, MWT, 64);
    strips_mc<64><<<497, 256, smem64>>>(Xt0h, MRST, MCST, MWT, G, CG, H);
    prefix_all_k<<<2080, 256>>>(G, CG, H);
    combine_mc<64, true><<<1024, 256, smem64>>>(Xt0h, WCT, G, CG, H, mb0, jb0, Yth);

    // ---- layer 1: Fin = 128 ----
    prep_k<<<(128 * 128) / 256, 256>>>(mw1, jw1, WCT, MRST, MCST, MWT, 128);
    strips_mc<128><<<497, 256, smem128>>>(Yth, MRST, MCST, MWT, G, CG, H);
    prefix_all_k<<<2080, 256>>>(G, CG, H);
    combine_mc<128, false><<<1024, 256, smem128>>>(Yth, WCT, G, CG, H, mb1, jb1, Yt2);

    // Yt2 [1024][8192] -> out [8192][1024]
    transpose_k<<<dim3(8192 / 32, 1024 / 32), tb>>>(out, Yt2, 1024, 8192);
}

// round 13
// speedup vs baseline: 1.9547x; 1.9547x over previous
#include <cuda_runtime.h>
#include <cuda_fp16.h>
#include <cstdint>

// LatticeCNN on GB300 — closed-form lattice conv decomposition + fp16 mma.sync.
// Round-7 base (best: 243.8us) + coalesced/parallelized weight-table prep.
//
// join conv  == pointwise with 2-D prefix-summed weights
// meet conv  == pointwise(suffix weights) + x-prefix row strips + y-prefix col
//               strips + 2-D-prefix corner term

#define ALPHA  0.5f
#define SLOPE  0.01f
#define S      32
#define FOUT   128

__device__ __forceinline__ uint32_t pack_f16x2(float lo, float hi) {
    uint32_t r;
    asm("cvt.rn.f16x2.f32 %0, %1, %2;" : "=r"(r) : "f"(hi), "f"(lo));
    return r;
}

__device__ __forceinline__ void mma16(float (&d)[4], const uint4& a,
                                      uint32_t b0, uint32_t b1) {
    asm volatile(
        "mma.sync.aligned.m16n8k16.row.col.f32.f16.f16.f32 "
        "{%0,%1,%2,%3}, {%4,%5,%6,%7}, {%8,%9}, {%0,%1,%2,%3};"
        : "+f"(d[0]), "+f"(d[1]), "+f"(d[2]), "+f"(d[3])
        : "r"(a.x), "r"(a.y), "r"(a.z), "r"(a.w), "r"(b0), "r"(b1));
}

// ---------------- device scratch (no allocation allowed) ----------------
__device__ float d_Xt0 [1024 * 64 * 64];     // layer0 input, pixel-major [p][m][f]
__device__ float d_Yt  [1024 * 64 * 128];    // layer0 out / layer1 in
__device__ float d_Yt2 [1024 * 64 * 128];    // layer1 out (pixel-major)
__device__ float d_WCT [225 * 128 * FOUT];   // combined pointwise weights [class][g][f]
__device__ float d_MRST[64 * 128 * FOUT];    // row-suffix weights  [a*8+q][g][f]
__device__ float d_MCST[64 * 128 * FOUT];    // col-suffix weights  [p*8+b][g][f]
__device__ float d_MWT [64 * 128 * FOUT];    // raw meet weights    [a*8+b][g][f]
__device__ float d_G   [224 * 64 * FOUT];    // row strip tiles  G[a][y]
__device__ float d_CG  [224 * 64 * FOUT];    // col strip tiles  CG[b][x]
__device__ float d_H   [49  * 64 * FOUT];    // corner tiles     H[a][b]

// ---------------- tiled transpose: dst[C][R] = src[R][C] ----------------
__global__ void transpose_k(float* __restrict__ dst, const float* __restrict__ src,
                            int R, int C)
{
    __shared__ float tile[32][33];
    int c0 = blockIdx.x * 32, r0 = blockIdx.y * 32;
    #pragma unroll
    for (int i = 0; i < 4; i++)
        tile[threadIdx.y + 8 * i][threadIdx.x] =
            src[(size_t)(r0 + threadIdx.y + 8 * i) * C + c0 + threadIdx.x];
    __syncthreads();
    #pragma unroll
    for (int i = 0; i < 4; i++)
        dst[(size_t)(c0 + threadIdx.y + 8 * i) * R + r0 + threadIdx.x] =
            tile[threadIdx.x][threadIdx.y + 8 * i];
}

// ---------------- per-layer weight-table prep (coalesced [g][f] writes) ----
// Thread owns output slot idx == g*Fin + f (f fastest -> consecutive lanes
// write consecutive floats in every table). blockIdx.y splits the work:
//   part 0      : MWT + MCST + MRST
//   parts 1..3  : WCT classes cx in [5*(part-1), 5*part)
__global__ void prep_k(const float* __restrict__ mw, const float* __restrict__ jw,
                       float* __restrict__ WCT, float* __restrict__ MRST,
                       float* __restrict__ MCST, float* __restrict__ MWT, int Fin)
{
    int idx = blockIdx.x * blockDim.x + threadIdx.x;
    if (idx >= Fin * FOUT) return;
    int f = idx % Fin, g = idx / Fin;
    int ss = Fin * FOUT;
    int src = f * FOUT + g;          // original [a][b][f][g] (strided read, L1-reused)
    int part = blockIdx.y;

    float m[8][8];
    #pragma unroll
    for (int a = 0; a < 8; a++)
        #pragma unroll
        for (int b = 0; b < 8; b++)
            m[a][b] = mw[(a * 8 + b) * ss + src];

    if (part == 0) {
        #pragma unroll
        for (int a = 0; a < 8; a++)
            #pragma unroll
            for (int b = 0; b < 8; b++)
                MWT[(a * 8 + b) * ss + idx] = m[a][b];
        {   // MCS[p][b] = sum_{a>=p} mw[a][b]
            float col[8];
            #pragma unroll
            for (int b = 0; b < 8; b++) col[b] = 0.f;
            #pragma unroll
            for (int p = 7; p >= 0; p--)
                #pragma unroll
                for (int b = 0; b < 8; b++) {
                    col[b] += m[p][b];
                    MCST[(p * 8 + b) * ss + idx] = col[b];
                }
        }
        #pragma unroll
        for (int a = 0; a < 8; a++) {    // MRS[a][q] = sum_{b>=q}
            #pragma unroll
            for (int q = 6; q >= 0; q--) m[a][q] += m[a][q + 1];
            #pragma unroll
            for (int q = 0; q < 8; q++) MRST[(a * 8 + q) * ss + idx] = m[a][q];
        }
        return;
    }

    // parts 1..3: full 2-D suffix of m, 2-D prefix of j, write WCT slice
    #pragma unroll
    for (int a = 0; a < 8; a++)
        #pragma unroll
        for (int q = 6; q >= 0; q--) m[a][q] += m[a][q + 1];
    #pragma unroll
    for (int b = 0; b < 8; b++)
        #pragma unroll
        for (int a = 6; a >= 0; a--) m[a][b] += m[a + 1][b];

    float j[8][8];
    #pragma unroll
    for (int a = 0; a < 8; a++)
        #pragma unroll
        for (int b = 0; b < 8; b++)
            j[a][b] = jw[(a * 8 + b) * ss + src];
    #pragma unroll
    for (int a = 0; a < 8; a++)
        #pragma unroll
        for (int b = 1; b < 8; b++) j[a][b] += j[a][b - 1];
    #pragma unroll
    for (int b = 0; b < 8; b++)
        #pragma unroll
        for (int a = 1; a < 8; a++) j[a][b] += j[a - 1][b];

    int cx0 = (part - 1) * 5;
    for (int cx = cx0; cx < cx0 + 5; cx++) {
        int ax = cx < 8 ? 0 : cx - 7;
        int jx = cx < 8 ? cx : 7;
        for (int cy = 0; cy < 15; cy++) {
            int ay = cy < 8 ? 0 : cy - 7;
            int jy = cy < 8 ? cy : 7;
            WCT[(cx * 15 + cy) * ss + idx] =
                (1.0f - ALPHA) * m[ax][ay] + ALPHA * j[jx][jy];
        }
    }
}

// ---------------- GEMM unit: [64 x FIN] * W^T[128 x FIN] -> acc regs -------
// 8 warps: warp (wm,wn) = (wid/4, wid%4) owns rows [wm*32,+32) x cols [wn*32,+32).
// smem: raw fp16 tiles, halfword stride LDh = FIN+8 (LDh/2 == 4 mod 32 ->
// every f16x2 fragment gather is a conflict-free LDS.32).
template <int FIN>
__device__ __forceinline__ void unit_gemm(const float* __restrict__ X,
                                          const float* __restrict__ W,
                                          __half* sm, float (&acc)[2][4][4])
{
    constexpr int LDh = FIN + 8;
    constexpr int V = FIN / 4;
    __half* Xs = sm;                 // [64][LDh]
    __half* Ws = sm + 64 * LDh;      // [128][LDh]
    const int tid = threadIdx.x;

    #pragma unroll
    for (int v = tid; v < 64 * V; v += 256) {
        int r = v / V, k = (v % V) * 4;
        float4 x = *(const float4*)(X + r * FIN + k);
        uint2 h;
        h.x = pack_f16x2(x.x, x.y);
        h.y = pack_f16x2(x.z, x.w);
        *(uint2*)(Xs + r * LDh + k) = h;
    }
    #pragma unroll
    for (int v = tid; v < 128 * V; v += 256) {
        int r = v / V, k = (v % V) * 4;
        float4 x = *(const float4*)(W + r * FIN + k);
        uint2 h;
        h.x = pack_f16x2(x.x, x.y);
        h.y = pack_f16x2(x.z, x.w);
        *(uint2*)(Ws + r * LDh + k) = h;
    }
    __syncthreads();

    const int lane = tid & 31, wid = tid >> 5;
    const int wm = wid >> 2, wn = wid & 3;
    const __half* Ax = Xs + (wm * 32 + (lane >> 2)) * LDh + (lane & 3) * 2;
    const __half* Bx = Ws + (wn * 32 + (lane >> 2)) * LDh + (lane & 3) * 2;

    #pragma unroll
    for (int kt = 0; kt < FIN / 16; kt++) {
        const int k0 = kt * 16;
        uint4 a0, a1;
        a0.x = *(const uint32_t*)(Ax + k0);
        a0.y = *(const uint32_t*)(Ax + 8 * LDh + k0);
        a0.z = *(const uint32_t*)(Ax + k0 + 8);
        a0.w = *(const uint32_t*)(Ax + 8 * LDh + k0 + 8);
        a1.x = *(const uint32_t*)(Ax + 16 * LDh + k0);
        a1.y = *(const uint32_t*)(Ax + 24 * LDh + k0);
        a1.z = *(const uint32_t*)(Ax + 16 * LDh + k0 + 8);
        a1.w = *(const uint32_t*)(Ax + 24 * LDh + k0 + 8);
        uint32_t b[4][2];
        #pragma unroll
        for (int nt = 0; nt < 4; nt++) {
            b[nt][0] = *(const uint32_t*)(Bx + nt * 8 * LDh + k0);
            b[nt][1] = *(const uint32_t*)(Bx + nt * 8 * LDh + k0 + 8);
        }
        #pragma unroll
        for (int nt = 0; nt < 4; nt++) {
            mma16(acc[0][nt], a0, b[nt][0], b[nt][1]);
            mma16(acc[1][nt], a1, b[nt][0], b[nt][1]);
        }
    }
}

// ---------------- strips/corner: 497 units, 1 per block ----------------
template <int FIN>
__global__ void __launch_bounds__(256) strips_mc(
    const float* __restrict__ Xt, const float* __restrict__ MRST,
    const float* __restrict__ MCST, const float* __restrict__ MWT,
    float* __restrict__ G, float* __restrict__ CG, float* __restrict__ H)
{
    extern __shared__ __half smh[];
    int u = blockIdx.x;
    size_t ss = (size_t)FIN * FOUT;
    const float* X; const float* W; float* dst;
    if (u < 224) {
        int a = u >> 5, Y = u & 31;
        int q = Y > 24 ? Y - 24 : 0;
        X = Xt + (size_t)((a + 24) * S + Y) * 64 * FIN;
        W = MRST + (size_t)(a * 8 + q) * ss;
        dst = G + (size_t)u * 64 * FOUT;
    } else if (u < 448) {
        int t = u - 224;
        int b = t >> 5, Xc = t & 31;
        int p = Xc > 24 ? Xc - 24 : 0;
        X = Xt + (size_t)(Xc * S + b + 24) * 64 * FIN;
        W = MCST + (size_t)(p * 8 + b) * ss;
        dst = CG + (size_t)t * 64 * FOUT;
    } else {
        int t = u - 448;
        int a = t / 7, b = t % 7;
        X = Xt + (size_t)((a + 24) * S + b + 24) * 64 * FIN;
        W = MWT + (size_t)(a * 8 + b) * ss;
        dst = H + (size_t)t * 64 * FOUT;
    }

    float acc[2][4][4] = {};
    unit_gemm<FIN>(X, W, smh, acc);

    int lane = threadIdx.x & 31, wid = threadIdx.x >> 5;
    int wm = wid >> 2, wn = wid & 3;
    int r0 = wm * 32 + (lane >> 2);
    #pragma unroll
    for (int mt = 0; mt < 2; mt++)
        #pragma unroll
        for (int nt = 0; nt < 4; nt++) {
            int g = wn * 32 + nt * 8 + (lane & 3) * 2;
            int r = r0 + mt * 16;
            *(float2*)(dst + r * FOUT + g)       = make_float2(acc[mt][nt][0], acc[mt][nt][1]);
            *(float2*)(dst + (r + 8) * FOUT + g) = make_float2(acc[mt][nt][2], acc[mt][nt][3]);
        }
}

// ---------------- merged prefix pass: rows(G) + rows(CG) + 2-D(H) ----------
__global__ void prefix_all_k(float* __restrict__ G, float* __restrict__ CG,
                             float* __restrict__ H)
{
    int bid = blockIdx.x;
    if (bid < 2048) {
        int t = bid * 256 + threadIdx.x;
        float* buf = (t < 32 * 8192) ? G : CG;
        int tt = t & (32 * 8192 - 1);
        int yy = tt >> 13, mg = tt & 8191;
        float run = 0.f;
        #pragma unroll
        for (int a = 0; a < 7; a++) {
            int idx = (a * 32 + yy) * 8192 + mg;
            run += buf[idx];
            buf[idx] = run;
        }
    } else {
        int mg = (bid - 2048) * 256 + threadIdx.x;
        float colA[7];
        #pragma unroll
        for (int b = 0; b < 7; b++) colA[b] = 0.f;
        #pragma unroll
        for (int a = 0; a < 7; a++) {
            float run = 0.f;
            #pragma unroll
            for (int b = 0; b < 7; b++) {
                int idx = (a * 7 + b) * 8192 + mg;
                run += H[idx];
                colA[b] += run;
                H[idx] = colA[b];
            }
        }
    }
}

// ---------------- combine: 1024 pixels, 1 per block ----------------
template <int FIN>
__global__ void __launch_bounds__(256) combine_mc(
    const float* __restrict__ Xt, const float* __restrict__ WCT,
    const float* __restrict__ Gc, const float* __restrict__ CGc,
    const float* __restrict__ Hc, const float* __restrict__ mb,
    const float* __restrict__ jb, float* __restrict__ Yout)
{
    extern __shared__ __half smh[];
    int p = blockIdx.x;
    int X = p >> 5, Y = p & 31;
    int cx = X <= 24 ? (X < 7 ? X : 7) : X - 17;
    int cy = Y <= 24 ? (Y < 7 ? Y : 7) : Y - 17;
    size_t ss = (size_t)FIN * FOUT;

    float acc[2][4][4] = {};
    unit_gemm<FIN>(Xt + (size_t)p * 64 * FIN,
                   WCT + (size_t)(cx * 15 + cy) * ss, smh, acc);

    const float ms = 1.0f - ALPHA;
    const float* Gp = (X >= 25) ? Gc + (size_t)((X - 25) * S + Y) * 64 * FOUT : 0;
    const float* Cp = (Y >= 25) ? CGc + (size_t)((Y - 25) * S + X) * 64 * FOUT : 0;
    const float* Hp = (X >= 25 && Y >= 25)
        ? Hc + (size_t)((X - 25) * 7 + (Y - 25)) * 64 * FOUT : 0;

    int lane = threadIdx.x & 31, wid = threadIdx.x >> 5;
    int wm = wid >> 2, wn = wid & 3;
    int r0 = wm * 32 + (lane >> 2);
    float* O = Yout + (size_t)p * 64 * FOUT;

    #pragma unroll
    for (int nt = 0; nt < 4; nt++) {
        int g = wn * 32 + nt * 8 + (lane & 3) * 2;
        float2 bias = make_float2(ms * mb[g]     + ALPHA * jb[g],
                                  ms * mb[g + 1] + ALPHA * jb[g + 1]);
        #pragma unroll
        for (int mt = 0; mt < 2; mt++) {
            #pragma unroll
            for (int half = 0; half < 2; half++) {
                int r = r0 + mt * 16 + half * 8;
                float v0 = acc[mt][nt][half * 2], v1 = acc[mt][nt][half * 2 + 1];
                if (Gp) {
                    float2 s2 = *(const float2*)(Gp + r * FOUT + g);
                    v0 += ms * s2.x; v1 += ms * s2.y;
                }
                if (Cp) {
                    float2 s2 = *(const float2*)(Cp + r * FOUT + g);
                    v0 += ms * s2.x; v1 += ms * s2.y;
                }
                if (Hp) {
                    float2 s2 = *(const float2*)(Hp + r * FOUT + g);
                    v0 += ms * s2.x; v1 += ms * s2.y;
                }
                v0 += bias.x; v1 += bias.y;
                v0 = fmaxf(v0, SLOPE * v0);
                v1 = fmaxf(v1, SLOPE * v1);
                *(float2*)(O + r * FOUT + g) = make_float2(v0, v1);
            }
        }
    }
}

// ---------------- host launch ----------------
extern "C" void kernel_launch(void* const* d_in, const int* in_sizes, int n_in,
                              void* d_out, int out_size)
{
    const float* x   = (const float*)d_in[0];
    const float* mw0 = (const float*)d_in[5];
    const float* mb0 = (const float*)d_in[6];
    const float* jw0 = (const float*)d_in[7];
    const float* jb0 = (const float*)d_in[8];
    const float* mw1 = (const float*)d_in[9];
    const float* mb1 = (const float*)d_in[10];
    const float* jw1 = (const float*)d_in[11];
    const float* jb1 = (const float*)d_in[12];
    float* out = (float*)d_out;

    float *Xt0, *Yt, *Yt2, *WCT, *MRST, *MCST, *MWT, *G, *CG, *H;
    cudaGetSymbolAddress((void**)&Xt0,  d_Xt0);
    cudaGetSymbolAddress((void**)&Yt,   d_Yt);
    cudaGetSymbolAddress((void**)&Yt2,  d_Yt2);
    cudaGetSymbolAddress((void**)&WCT,  d_WCT);
    cudaGetSymbolAddress((void**)&MRST, d_MRST);
    cudaGetSymbolAddress((void**)&MCST, d_MCST);
    cudaGetSymbolAddress((void**)&MWT,  d_MWT);
    cudaGetSymbolAddress((void**)&G,    d_G);
    cudaGetSymbolAddress((void**)&CG,   d_CG);
    cudaGetSymbolAddress((void**)&H,    d_H);

    const int smem64  = 192 * (64 + 8)  * 2;   // 27648 B
    const int smem128 = 192 * (128 + 8) * 2;   // 52224 B
    cudaFuncSetAttribute(strips_mc<64>,   cudaFuncAttributeMaxDynamicSharedMemorySize, smem64);
    cudaFuncSetAttribute(combine_mc<64>,  cudaFuncAttributeMaxDynamicSharedMemorySize, smem64);
    cudaFuncSetAttribute(strips_mc<128>,  cudaFuncAttributeMaxDynamicSharedMemorySize, smem128);
    cudaFuncSetAttribute(combine_mc<128>, cudaFuncAttributeMaxDynamicSharedMemorySize, smem128);

    dim3 tb(32, 8);
    // x [64*64][1024] -> Xt0 [1024][64*64]
    transpose_k<<<dim3(1024 / 32, 4096 / 32), tb>>>(Xt0, x, 4096, 1024);

    // ---- layer 0: Fin = 64 ----
    prep_k<<<dim3((64 * 128) / 256, 4), 256>>>(mw0, jw0, WCT, MRST, MCST, MWT, 64);
    strips_mc<64><<<497, 256, smem64>>>(Xt0, MRST, MCST, MWT, G, CG, H);
    prefix_all_k<<<2080, 256>>>(G, CG, H);
    combine_mc<64><<<1024, 256, smem64>>>(Xt0, WCT, G, CG, H, mb0, jb0, Yt);

    // ---- layer 1: Fin = 128 ----
    prep_k<<<dim3((128 * 128) / 256, 4), 256>>>(mw1, jw1, WCT, MRST, MCST, MWT, 128);
    strips_mc<128><<<497, 256, smem128>>>(Yt, MRST, MCST, MWT, G, CG, H);
    prefix_all_k<<<2080, 256>>>(G, CG, H);
    combine_mc<128><<<1024, 256, smem128>>>(Yt, WCT, G, CG, H, mb1, jb1, Yt2);

    // Yt2 [1024][8192] -> out [8192][1024]
    transpose_k<<<dim3(8192 / 32, 1024 / 32), tb>>>(out, Yt2, 1024, 8192);
}

// round 14
// speedup vs baseline: 2.1658x; 1.1080x over previous
#include <cuda_runtime.h>
#include <cuda_fp16.h>
#include <cstdint>

// LatticeCNN on GB300 — closed-form lattice conv decomposition + fp16 mma.sync.
// R13 base (168.7us: coalesced prep) + fp16-resident activations/weights
// (now that prep writes are coalesced, fp16 tables/tensors halve GEMM-side
// traffic and delete all in-kernel conversions).
//
// join conv  == pointwise with 2-D prefix-summed weights
// meet conv  == pointwise(suffix weights) + x-prefix row strips + y-prefix col
//               strips + 2-D-prefix corner term

#define ALPHA  0.5f
#define SLOPE  0.01f
#define S      32
#define FOUT   128

__device__ __forceinline__ uint32_t pack_f16x2(float lo, float hi) {
    uint32_t r;
    asm("cvt.rn.f16x2.f32 %0, %1, %2;" : "=r"(r) : "f"(hi), "f"(lo));
    return r;
}

__device__ __forceinline__ void mma16(float (&d)[4], const uint4& a,
                                      uint32_t b0, uint32_t b1) {
    asm volatile(
        "mma.sync.aligned.m16n8k16.row.col.f32.f16.f16.f32 "
        "{%0,%1,%2,%3}, {%4,%5,%6,%7}, {%8,%9}, {%0,%1,%2,%3};"
        : "+f"(d[0]), "+f"(d[1]), "+f"(d[2]), "+f"(d[3])
        : "r"(a.x), "r"(a.y), "r"(a.z), "r"(a.w), "r"(b0), "r"(b1));
}

// ---------------- device scratch (no allocation allowed) ----------------
__device__ __half d_Xt0h[1024 * 64 * 64];    // layer0 input, pixel-major fp16
__device__ __half d_Yth [1024 * 64 * 128];   // layer0 out / layer1 in, fp16
__device__ float  d_Yt2 [1024 * 64 * 128];   // layer1 out (pixel-major, fp32)
__device__ __half d_WCT [225 * 128 * FOUT];  // pointwise weights [class][g][f]
__device__ __half d_MRST[64 * 128 * FOUT];   // row-suffix  [a*8+q][g][f]
__device__ __half d_MCST[64 * 128 * FOUT];   // col-suffix  [p*8+b][g][f]
__device__ __half d_MWT [64 * 128 * FOUT];   // raw meet    [a*8+b][g][f]
__device__ float  d_G   [224 * 64 * FOUT];   // row strip tiles  G[a][y]
__device__ float  d_CG  [224 * 64 * FOUT];   // col strip tiles  CG[b][x]
__device__ float  d_H   [49  * 64 * FOUT];   // corner tiles     H[a][b]

// ---------------- transposes ----------------
// dst[C][R] fp16 = src[R][C] fp32, vectorized coalesced 4B writes.
__global__ void transpose_h_k(__half* __restrict__ dst, const float* __restrict__ src,
                              int R, int C)
{
    __shared__ float tile[32][33];
    int c0 = blockIdx.x * 32, r0 = blockIdx.y * 32;
    #pragma unroll
    for (int i = 0; i < 4; i++)
        tile[threadIdx.y + 8 * i][threadIdx.x] =
            src[(size_t)(r0 + threadIdx.y + 8 * i) * C + c0 + threadIdx.x];
    __syncthreads();
    int tid = threadIdx.y * 32 + threadIdx.x;
    int rp = tid & 15, cc = tid >> 4;        // 16 row-pairs x 16 cols per pass
    #pragma unroll
    for (int pass = 0; pass < 2; pass++) {
        int c = cc + pass * 16;
        uint32_t v = pack_f16x2(tile[2 * rp][c], tile[2 * rp + 1][c]);
        *(uint32_t*)(dst + (size_t)(c0 + c) * R + r0 + 2 * rp) = v;
    }
}

__global__ void transpose_k(float* __restrict__ dst, const float* __restrict__ src,
                            int R, int C)
{
    __shared__ float tile[32][33];
    int c0 = blockIdx.x * 32, r0 = blockIdx.y * 32;
    #pragma unroll
    for (int i = 0; i < 4; i++)
        tile[threadIdx.y + 8 * i][threadIdx.x] =
            src[(size_t)(r0 + threadIdx.y + 8 * i) * C + c0 + threadIdx.x];
    __syncthreads();
    #pragma unroll
    for (int i = 0; i < 4; i++)
        dst[(size_t)(c0 + threadIdx.y + 8 * i) * R + r0 + threadIdx.x] =
            tile[threadIdx.x][threadIdx.y + 8 * i];
}

// ---------------- per-layer weight-table prep (coalesced fp16 writes) ------
// Thread owns output slot idx == g*Fin + f (f fastest -> consecutive lanes
// write consecutive halves in every table). blockIdx.y splits the work:
//   part 0      : MWT + MCST + MRST
//   parts 1..3  : WCT classes cx in [5*(part-1), 5*part)
__global__ void prep_k(const float* __restrict__ mw, const float* __restrict__ jw,
                       __half* __restrict__ WCT, __half* __restrict__ MRST,
                       __half* __restrict__ MCST, __half* __restrict__ MWT, int Fin)
{
    int idx = blockIdx.x * blockDim.x + threadIdx.x;
    if (idx >= Fin * FOUT) return;
    int f = idx % Fin, g = idx / Fin;
    int ss = Fin * FOUT;
    int src = f * FOUT + g;          // original [a][b][f][g] (strided read, L1-reused)
    int part = blockIdx.y;

    float m[8][8];
    #pragma unroll
    for (int a = 0; a < 8; a++)
        #pragma unroll
        for (int b = 0; b < 8; b++)
            m[a][b] = mw[(a * 8 + b) * ss + src];

    if (part == 0) {
        #pragma unroll
        for (int a = 0; a < 8; a++)
            #pragma unroll
            for (int b = 0; b < 8; b++)
                MWT[(a * 8 + b) * ss + idx] = __float2half_rn(m[a][b]);
        {   // MCS[p][b] = sum_{a>=p} mw[a][b]
            float col[8];
            #pragma unroll
            for (int b = 0; b < 8; b++) col[b] = 0.f;
            #pragma unroll
            for (int p = 7; p >= 0; p--)
                #pragma unroll
                for (int b = 0; b < 8; b++) {
                    col[b] += m[p][b];
                    MCST[(p * 8 + b) * ss + idx] = __float2half_rn(col[b]);
                }
        }
        #pragma unroll
        for (int a = 0; a < 8; a++) {    // MRS[a][q] = sum_{b>=q}
            #pragma unroll
            for (int q = 6; q >= 0; q--) m[a][q] += m[a][q + 1];
            #pragma unroll
            for (int q = 0; q < 8; q++)
                MRST[(a * 8 + q) * ss + idx] = __float2half_rn(m[a][q]);
        }
        return;
    }

    // parts 1..3: full 2-D suffix of m, 2-D prefix of j, write WCT slice
    #pragma unroll
    for (int a = 0; a < 8; a++)
        #pragma unroll
        for (int q = 6; q >= 0; q--) m[a][q] += m[a][q + 1];
    #pragma unroll
    for (int b = 0; b < 8; b++)
        #pragma unroll
        for (int a = 6; a >= 0; a--) m[a][b] += m[a + 1][b];

    float j[8][8];
    #pragma unroll
    for (int a = 0; a < 8; a++)
        #pragma unroll
        for (int b = 0; b < 8; b++)
            j[a][b] = jw[(a * 8 + b) * ss + src];
    #pragma unroll
    for (int a = 0; a < 8; a++)
        #pragma unroll
        for (int b = 1; b < 8; b++) j[a][b] += j[a][b - 1];
    #pragma unroll
    for (int b = 0; b < 8; b++)
        #pragma unroll
        for (int a = 1; a < 8; a++) j[a][b] += j[a - 1][b];

    int cx0 = (part - 1) * 5;
    for (int cx = cx0; cx < cx0 + 5; cx++) {
        int ax = cx < 8 ? 0 : cx - 7;
        int jx = cx < 8 ? cx : 7;
        for (int cy = 0; cy < 15; cy++) {
            int ay = cy < 8 ? 0 : cy - 7;
            int jy = cy < 8 ? cy : 7;
            WCT[(cx * 15 + cy) * ss + idx] =
                __float2half_rn((1.0f - ALPHA) * m[ax][ay] + ALPHA * j[jx][jy]);
        }
    }
}

// ---------------- GEMM unit: [64 x FIN] * W^T[128 x FIN] -> acc regs -------
// 8 warps: warp (wm,wn) = (wid/4, wid%4) owns rows [wm*32,+32) x cols [wn*32,+32).
// smem: raw fp16 tiles, halfword stride LDh = FIN+8 (LDh/2 == 4 mod 32 ->
// every f16x2 fragment gather is a conflict-free LDS.32). Staging is plain
// 16B LDG -> 16B STS (data already fp16 in global).
template <int FIN>
__device__ __forceinline__ void unit_gemm(const __half* __restrict__ X,
                                          const __half* __restrict__ W,
                                          __half* sm, float (&acc)[2][4][4])
{
    constexpr int LDh = FIN + 8;
    constexpr int CR  = FIN / 8;     // 16B chunks per row
    __half* Xs = sm;                 // [64][LDh]
    __half* Ws = sm + 64 * LDh;      // [128][LDh]
    const int tid = threadIdx.x;

    #pragma unroll
    for (int c = tid; c < 64 * CR; c += 256) {
        int r = c / CR, k = (c % CR) * 8;
        *(uint4*)(Xs + r * LDh + k) = *(const uint4*)(X + r * FIN + k);
    }
    #pragma unroll
    for (int c = tid; c < 128 * CR; c += 256) {
        int r = c / CR, k = (c % CR) * 8;
        *(uint4*)(Ws + r * LDh + k) = *(const uint4*)(W + r * FIN + k);
    }
    __syncthreads();

    const int lane = tid & 31, wid = tid >> 5;
    const int wm = wid >> 2, wn = wid & 3;
    const __half* Ax = Xs + (wm * 32 + (lane >> 2)) * LDh + (lane & 3) * 2;
    const __half* Bx = Ws + (wn * 32 + (lane >> 2)) * LDh + (lane & 3) * 2;

    #pragma unroll
    for (int kt = 0; kt < FIN / 16; kt++) {
        const int k0 = kt * 16;
        uint4 a0, a1;
        a0.x = *(const uint32_t*)(Ax + k0);
        a0.y = *(const uint32_t*)(Ax + 8 * LDh + k0);
        a0.z = *(const uint32_t*)(Ax + k0 + 8);
        a0.w = *(const uint32_t*)(Ax + 8 * LDh + k0 + 8);
        a1.x = *(const uint32_t*)(Ax + 16 * LDh + k0);
        a1.y = *(const uint32_t*)(Ax + 24 * LDh + k0);
        a1.z = *(const uint32_t*)(Ax + 16 * LDh + k0 + 8);
        a1.w = *(const uint32_t*)(Ax + 24 * LDh + k0 + 8);
        uint32_t b[4][2];
        #pragma unroll
        for (int nt = 0; nt < 4; nt++) {
            b[nt][0] = *(const uint32_t*)(Bx + nt * 8 * LDh + k0);
            b[nt][1] = *(const uint32_t*)(Bx + nt * 8 * LDh + k0 + 8);
        }
        #pragma unroll
        for (int nt = 0; nt < 4; nt++) {
            mma16(acc[0][nt], a0, b[nt][0], b[nt][1]);
            mma16(acc[1][nt], a1, b[nt][0], b[nt][1]);
        }
    }
}

// ---------------- strips/corner: 497 units, 1 per block ----------------
template <int FIN>
__global__ void __launch_bounds__(256) strips_mc(
    const __half* __restrict__ Xt, const __half* __restrict__ MRST,
    const __half* __restrict__ MCST, const __half* __restrict__ MWT,
    float* __restrict__ G, float* __restrict__ CG, float* __restrict__ H)
{
    extern __shared__ __half smh[];
    int u = blockIdx.x;
    size_t ss = (size_t)FIN * FOUT;
    const __half* X; const __half* W; float* dst;
    if (u < 224) {
        int a = u >> 5, Y = u & 31;
        int q = Y > 24 ? Y - 24 : 0;
        X = Xt + (size_t)((a + 24) * S + Y) * 64 * FIN;
        W = MRST + (size_t)(a * 8 + q) * ss;
        dst = G + (size_t)u * 64 * FOUT;
    } else if (u < 448) {
        int t = u - 224;
        int b = t >> 5, Xc = t & 31;
        int p = Xc > 24 ? Xc - 24 : 0;
        X = Xt + (size_t)(Xc * S + b + 24) * 64 * FIN;
        W = MCST + (size_t)(p * 8 + b) * ss;
        dst = CG + (size_t)t * 64 * FOUT;
    } else {
        int t = u - 448;
        int a = t / 7, b = t % 7;
        X = Xt + (size_t)((a + 24) * S + b + 24) * 64 * FIN;
        W = MWT + (size_t)(a * 8 + b) * ss;
        dst = H + (size_t)t * 64 * FOUT;
    }

    float acc[2][4][4] = {};
    unit_gemm<FIN>(X, W, smh, acc);

    int lane = threadIdx.x & 31, wid = threadIdx.x >> 5;
    int wm = wid >> 2, wn = wid & 3;
    int r0 = wm * 32 + (lane >> 2);
    #pragma unroll
    for (int mt = 0; mt < 2; mt++)
        #pragma unroll
        for (int nt = 0; nt < 4; nt++) {
            int g = wn * 32 + nt * 8 + (lane & 3) * 2;
            int r = r0 + mt * 16;
            *(float2*)(dst + r * FOUT + g)       = make_float2(acc[mt][nt][0], acc[mt][nt][1]);
            *(float2*)(dst + (r + 8) * FOUT + g) = make_float2(acc[mt][nt][2], acc[mt][nt][3]);
        }
}

// ---------------- merged prefix pass: rows(G) + rows(CG) + 2-D(H) ----------
__global__ void prefix_all_k(float* __restrict__ G, float* __restrict__ CG,
                             float* __restrict__ H)
{
    int bid = blockIdx.x;
    if (bid < 2048) {
        int t = bid * 256 + threadIdx.x;
        float* buf = (t < 32 * 8192) ? G : CG;
        int tt = t & (32 * 8192 - 1);
        int yy = tt >> 13, mg = tt & 8191;
        float run = 0.f;
        #pragma unroll
        for (int a = 0; a < 7; a++) {
            int idx = (a * 32 + yy) * 8192 + mg;
            run += buf[idx];
            buf[idx] = run;
        }
    } else {
        int mg = (bid - 2048) * 256 + threadIdx.x;
        float colA[7];
        #pragma unroll
        for (int b = 0; b < 7; b++) colA[b] = 0.f;
        #pragma unroll
        for (int a = 0; a < 7; a++) {
            float run = 0.f;
            #pragma unroll
            for (int b = 0; b < 7; b++) {
                int idx = (a * 7 + b) * 8192 + mg;
                run += H[idx];
                colA[b] += run;
                H[idx] = colA[b];
            }
        }
    }
}

// ---------------- combine: 1024 pixels, 1 per block ----------------
template <int FIN, bool OUT_HALF>
__global__ void __launch_bounds__(256) combine_mc(
    const __half* __restrict__ Xt, const __half* __restrict__ WCT,
    const float* __restrict__ Gc, const float* __restrict__ CGc,
    const float* __restrict__ Hc, const float* __restrict__ mb,
    const float* __restrict__ jb, void* __restrict__ Yout)
{
    extern __shared__ __half smh[];
    int p = blockIdx.x;
    int X = p >> 5, Y = p & 31;
    int cx = X <= 24 ? (X < 7 ? X : 7) : X - 17;
    int cy = Y <= 24 ? (Y < 7 ? Y : 7) : Y - 17;
    size_t ss = (size_t)FIN * FOUT;

    float acc[2][4][4] = {};
    unit_gemm<FIN>(Xt + (size_t)p * 64 * FIN,
                   WCT + (size_t)(cx * 15 + cy) * ss, smh, acc);

    const float ms = 1.0f - ALPHA;
    const float* Gp = (X >= 25) ? Gc + (size_t)((X - 25) * S + Y) * 64 * FOUT : 0;
    const float* Cp = (Y >= 25) ? CGc + (size_t)((Y - 25) * S + X) * 64 * FOUT : 0;
    const float* Hp = (X >= 25 && Y >= 25)
        ? Hc + (size_t)((X - 25) * 7 + (Y - 25)) * 64 * FOUT : 0;

    int lane = threadIdx.x & 31, wid = threadIdx.x >> 5;
    int wm = wid >> 2, wn = wid & 3;
    int r0 = wm * 32 + (lane >> 2);

    #pragma unroll
    for (int nt = 0; nt < 4; nt++) {
        int g = wn * 32 + nt * 8 + (lane & 3) * 2;
        float2 bias = make_float2(ms * mb[g]     + ALPHA * jb[g],
                                  ms * mb[g + 1] + ALPHA * jb[g + 1]);
        #pragma unroll
        for (int mt = 0; mt < 2; mt++) {
            #pragma unroll
            for (int half = 0; half < 2; half++) {
                int r = r0 + mt * 16 + half * 8;
                float v0 = acc[mt][nt][half * 2], v1 = acc[mt][nt][half * 2 + 1];
                if (Gp) {
                    float2 s2 = *(const float2*)(Gp + r * FOUT + g);
                    v0 += ms * s2.x; v1 += ms * s2.y;
                }
                if (Cp) {
                    float2 s2 = *(const float2*)(Cp + r * FOUT + g);
                    v0 += ms * s2.x; v1 += ms * s2.y;
                }
                if (Hp) {
                    float2 s2 = *(const float2*)(Hp + r * FOUT + g);
                    v0 += ms * s2.x; v1 += ms * s2.y;
                }
                v0 += bias.x; v1 += bias.y;
                v0 = fmaxf(v0, SLOPE * v0);
                v1 = fmaxf(v1, SLOPE * v1);
                if (OUT_HALF) {
                    __half* O = (__half*)Yout + (size_t)p * 64 * FOUT;
                    *(uint32_t*)(O + r * FOUT + g) = pack_f16x2(v0, v1);
                } else {
                    float* O = (float*)Yout + (size_t)p * 64 * FOUT;
                    *(float2*)(O + r * FOUT + g) = make_float2(v0, v1);
                }
            }
        }
    }
}

// ---------------- host launch ----------------
extern "C" void kernel_launch(void* const* d_in, const int* in_sizes, int n_in,
                              void* d_out, int out_size)
{
    const float* x   = (const float*)d_in[0];
    const float* mw0 = (const float*)d_in[5];
    const float* mb0 = (const float*)d_in[6];
    const float* jw0 = (const float*)d_in[7];
    const float* jb0 = (const float*)d_in[8];
    const float* mw1 = (const float*)d_in[9];
    const float* mb1 = (const float*)d_in[10];
    const float* jw1 = (const float*)d_in[11];
    const float* jb1 = (const float*)d_in[12];
    float* out = (float*)d_out;

    __half *Xt0h, *Yth, *WCT, *MRST, *MCST, *MWT;
    float *Yt2, *G, *CG, *H;
    cudaGetSymbolAddress((void**)&Xt0h, d_Xt0h);
    cudaGetSymbolAddress((void**)&Yth,  d_Yth);
    cudaGetSymbolAddress((void**)&Yt2,  d_Yt2);
    cudaGetSymbolAddress((void**)&WCT,  d_WCT);
    cudaGetSymbolAddress((void**)&MRST, d_MRST);
    cudaGetSymbolAddress((void**)&MCST, d_MCST);
    cudaGetSymbolAddress((void**)&MWT,  d_MWT);
    cudaGetSymbolAddress((void**)&G,    d_G);
    cudaGetSymbolAddress((void**)&CG,   d_CG);
    cudaGetSymbolAddress((void**)&H,    d_H);

    const int smem64  = 192 * (64 + 8)  * 2;   // 27648 B
    const int smem128 = 192 * (128 + 8) * 2;   // 52224 B
    cudaFuncSetAttribute(strips_mc<64>,  cudaFuncAttributeMaxDynamicSharedMemorySize, smem64);
    cudaFuncSetAttribute(combine_mc<64, true>,
                         cudaFuncAttributeMaxDynamicSharedMemorySize, smem64);
    cudaFuncSetAttribute(strips_mc<128>, cudaFuncAttributeMaxDynamicSharedMemorySize, smem128);
    cudaFuncSetAttribute(combine_mc<128, false>,
                         cudaFuncAttributeMaxDynamicSharedMemorySize, smem128);

    dim3 tb(32, 8);
    // x [4096][1024] fp32 -> Xt0h [1024][4096] fp16
    transpose_h_k<<<dim3(1024 / 32, 4096 / 32), tb>>>(Xt0h, x, 4096, 1024);

    // ---- layer 0: Fin = 64 ----
    prep_k<<<dim3((64 * 128) / 256, 4), 256>>>(mw0, jw0, WCT, MRST, MCST, MWT, 64);
    strips_mc<64><<<497, 256, smem64>>>(Xt0h, MRST, MCST, MWT, G, CG, H);
    prefix_all_k<<<2080, 256>>>(G, CG, H);
    combine_mc<64, true><<<1024, 256, smem64>>>(Xt0h, WCT, G, CG, H, mb0, jb0, Yth);

    // ---- layer 1: Fin = 128 ----
    prep_k<<<dim3((128 * 128) / 256, 4), 256>>>(mw1, jw1, WCT, MRST, MCST, MWT, 128);
    strips_mc<128><<<497, 256, smem128>>>(Yth, MRST, MCST, MWT, G, CG, H);
    prefix_all_k<<<2080, 256>>>(G, CG, H);
    combine_mc<128, false><<<1024, 256, smem128>>>(Yth, WCT, G, CG, H, mb1, jb1, Yt2);

    // Yt2 [1024][8192] -> out [8192][1024]
    transpose_k<<<dim3(8192 / 32, 1024 / 32), tb>>>(out, Yt2, 1024, 8192);
}

// round 15
// speedup vs baseline: 2.2043x; 1.0178x over previous
#include <cuda_runtime.h>
#include <cuda_fp16.h>
#include <cstdint>

// LatticeCNN on GB300 — closed-form lattice conv decomposition + fp16 mma.sync.
// R14 base (152.3us: coalesced prep + fp16-resident data) + cp.async staging
// (same 1-unit/block structure; LDGSTS removes the register roundtrip so all
// staging chunks are in flight at once — the kernels are L2-latency-bound).
//
// join conv  == pointwise with 2-D prefix-summed weights
// meet conv  == pointwise(suffix weights) + x-prefix row strips + y-prefix col
//               strips + 2-D-prefix corner term

#define ALPHA  0.5f
#define SLOPE  0.01f
#define S      32
#define FOUT   128

__device__ __forceinline__ uint32_t pack_f16x2(float lo, float hi) {
    uint32_t r;
    asm("cvt.rn.f16x2.f32 %0, %1, %2;" : "=r"(r) : "f"(hi), "f"(lo));
    return r;
}
__device__ __forceinline__ uint32_t smem_u32(const void* p) {
    uint32_t a;
    asm("{ .reg .u64 t; cvta.to.shared.u64 t, %1; cvt.u32.u64 %0, t; }"
        : "=r"(a) : "l"(p));
    return a;
}
#define CP16(dst, src) \
    asm volatile("cp.async.cg.shared.global [%0], [%1], 16;" \
                 :: "r"(dst), "l"(src) : "memory")
#define CP_COMMIT() asm volatile("cp.async.commit_group;" ::: "memory")
#define CP_WAIT0()  asm volatile("cp.async.wait_group 0;" ::: "memory")

__device__ __forceinline__ void mma16(float (&d)[4], const uint4& a,
                                      uint32_t b0, uint32_t b1) {
    asm volatile(
        "mma.sync.aligned.m16n8k16.row.col.f32.f16.f16.f32 "
        "{%0,%1,%2,%3}, {%4,%5,%6,%7}, {%8,%9}, {%0,%1,%2,%3};"
        : "+f"(d[0]), "+f"(d[1]), "+f"(d[2]), "+f"(d[3])
        : "r"(a.x), "r"(a.y), "r"(a.z), "r"(a.w), "r"(b0), "r"(b1));
}

// ---------------- device scratch (no allocation allowed) ----------------
__device__ __half d_Xt0h[1024 * 64 * 64];    // layer0 input, pixel-major fp16
__device__ __half d_Yth [1024 * 64 * 128];   // layer0 out / layer1 in, fp16
__device__ float  d_Yt2 [1024 * 64 * 128];   // layer1 out (pixel-major, fp32)
__device__ __half d_WCT [225 * 128 * FOUT];  // pointwise weights [class][g][f]
__device__ __half d_MRST[64 * 128 * FOUT];   // row-suffix  [a*8+q][g][f]
__device__ __half d_MCST[64 * 128 * FOUT];   // col-suffix  [p*8+b][g][f]
__device__ __half d_MWT [64 * 128 * FOUT];   // raw meet    [a*8+b][g][f]
__device__ float  d_G   [224 * 64 * FOUT];   // row strip tiles  G[a][y]
__device__ float  d_CG  [224 * 64 * FOUT];   // col strip tiles  CG[b][x]
__device__ float  d_H   [49  * 64 * FOUT];   // corner tiles     H[a][b]

// ---------------- transposes ----------------
// dst[C][R] fp16 = src[R][C] fp32, vectorized coalesced 4B writes.
__global__ void transpose_h_k(__half* __restrict__ dst, const float* __restrict__ src,
                              int R, int C)
{
    __shared__ float tile[32][33];
    int c0 = blockIdx.x * 32, r0 = blockIdx.y * 32;
    #pragma unroll
    for (int i = 0; i < 4; i++)
        tile[threadIdx.y + 8 * i][threadIdx.x] =
            src[(size_t)(r0 + threadIdx.y + 8 * i) * C + c0 + threadIdx.x];
    __syncthreads();
    int tid = threadIdx.y * 32 + threadIdx.x;
    int rp = tid & 15, cc = tid >> 4;        // 16 row-pairs x 16 cols per pass
    #pragma unroll
    for (int pass = 0; pass < 2; pass++) {
        int c = cc + pass * 16;
        uint32_t v = pack_f16x2(tile[2 * rp][c], tile[2 * rp + 1][c]);
        *(uint32_t*)(dst + (size_t)(c0 + c) * R + r0 + 2 * rp) = v;
    }
}

__global__ void transpose_k(float* __restrict__ dst, const float* __restrict__ src,
                            int R, int C)
{
    __shared__ float tile[32][33];
    int c0 = blockIdx.x * 32, r0 = blockIdx.y * 32;
    #pragma unroll
    for (int i = 0; i < 4; i++)
        tile[threadIdx.y + 8 * i][threadIdx.x] =
            src[(size_t)(r0 + threadIdx.y + 8 * i) * C + c0 + threadIdx.x];
    __syncthreads();
    #pragma unroll
    for (int i = 0; i < 4; i++)
        dst[(size_t)(c0 + threadIdx.y + 8 * i) * R + r0 + threadIdx.x] =
            tile[threadIdx.x][threadIdx.y + 8 * i];
}

// ---------------- per-layer weight-table prep (coalesced fp16 writes) ------
__global__ void prep_k(const float* __restrict__ mw, const float* __restrict__ jw,
                       __half* __restrict__ WCT, __half* __restrict__ MRST,
                       __half* __restrict__ MCST, __half* __restrict__ MWT, int Fin)
{
    int idx = blockIdx.x * blockDim.x + threadIdx.x;
    if (idx >= Fin * FOUT) return;
    int f = idx % Fin, g = idx / Fin;
    int ss = Fin * FOUT;
    int src = f * FOUT + g;          // original [a][b][f][g] (strided read, L1-reused)
    int part = blockIdx.y;

    float m[8][8];
    #pragma unroll
    for (int a = 0; a < 8; a++)
        #pragma unroll
        for (int b = 0; b < 8; b++)
            m[a][b] = mw[(a * 8 + b) * ss + src];

    if (part == 0) {
        #pragma unroll
        for (int a = 0; a < 8; a++)
            #pragma unroll
            for (int b = 0; b < 8; b++)
                MWT[(a * 8 + b) * ss + idx] = __float2half_rn(m[a][b]);
        {   // MCS[p][b] = sum_{a>=p} mw[a][b]
            float col[8];
            #pragma unroll
            for (int b = 0; b < 8; b++) col[b] = 0.f;
            #pragma unroll
            for (int p = 7; p >= 0; p--)
                #pragma unroll
                for (int b = 0; b < 8; b++) {
                    col[b] += m[p][b];
                    MCST[(p * 8 + b) * ss + idx] = __float2half_rn(col[b]);
                }
        }
        #pragma unroll
        for (int a = 0; a < 8; a++) {    // MRS[a][q] = sum_{b>=q}
            #pragma unroll
            for (int q = 6; q >= 0; q--) m[a][q] += m[a][q + 1];
            #pragma unroll
            for (int q = 0; q < 8; q++)
                MRST[(a * 8 + q) * ss + idx] = __float2half_rn(m[a][q]);
        }
        return;
    }

    // parts 1..3: full 2-D suffix of m, 2-D prefix of j, write WCT slice
    #pragma unroll
    for (int a = 0; a < 8; a++)
        #pragma unroll
        for (int q = 6; q >= 0; q--) m[a][q] += m[a][q + 1];
    #pragma unroll
    for (int b = 0; b < 8; b++)
        #pragma unroll
        for (int a = 6; a >= 0; a--) m[a][b] += m[a + 1][b];

    float j[8][8];
    #pragma unroll
    for (int a = 0; a < 8; a++)
        #pragma unroll
        for (int b = 0; b < 8; b++)
            j[a][b] = jw[(a * 8 + b) * ss + src];
    #pragma unroll
    for (int a = 0; a < 8; a++)
        #pragma unroll
        for (int b = 1; b < 8; b++) j[a][b] += j[a][b - 1];
    #pragma unroll
    for (int b = 0; b < 8; b++)
        #pragma unroll
        for (int a = 1; a < 8; a++) j[a][b] += j[a - 1][b];

    int cx0 = (blockIdx.y - 1) * 5;
    for (int cx = cx0; cx < cx0 + 5; cx++) {
        int ax = cx < 8 ? 0 : cx - 7;
        int jx = cx < 8 ? cx : 7;
        for (int cy = 0; cy < 15; cy++) {
            int ay = cy < 8 ? 0 : cy - 7;
            int jy = cy < 8 ? cy : 7;
            WCT[(cx * 15 + cy) * ss + idx] =
                __float2half_rn((1.0f - ALPHA) * m[ax][ay] + ALPHA * j[jx][jy]);
        }
    }
}

// ---------------- GEMM unit: [64 x FIN] * W^T[128 x FIN] -> acc regs -------
// 8 warps: warp (wm,wn) = (wid/4, wid%4) owns rows [wm*32,+32) x cols [wn*32,+32).
// smem: raw fp16 tiles, halfword stride LDh = FIN+8 (LDh/2 == 4 mod 32 ->
// every f16x2 fragment gather is a conflict-free LDS.32). Staging via
// cp.async.cg 16B (LDGSTS): all chunks in flight at once, no register roundtrip.
template <int FIN>
__device__ __forceinline__ void unit_gemm(const __half* __restrict__ X,
                                          const __half* __restrict__ W,
                                          __half* sm, float (&acc)[2][4][4])
{
    constexpr int LDh = FIN + 8;
    constexpr int CR  = FIN / 8;     // 16B chunks per row
    __half* Xs = sm;                 // [64][LDh]
    __half* Ws = sm + 64 * LDh;      // [128][LDh]
    const int tid = threadIdx.x;
    const uint32_t xs_base = smem_u32(Xs);
    const uint32_t ws_base = smem_u32(Ws);

    #pragma unroll
    for (int c = tid; c < 64 * CR; c += 256) {
        int r = c / CR, k = (c % CR) * 8;
        CP16(xs_base + (r * LDh + k) * 2, X + r * FIN + k);
    }
    #pragma unroll
    for (int c = tid; c < 128 * CR; c += 256) {
        int r = c / CR, k = (c % CR) * 8;
        CP16(ws_base + (r * LDh + k) * 2, W + r * FIN + k);
    }
    CP_COMMIT();
    CP_WAIT0();
    __syncthreads();

    const int lane = tid & 31, wid = tid >> 5;
    const int wm = wid >> 2, wn = wid & 3;
    const __half* Ax = Xs + (wm * 32 + (lane >> 2)) * LDh + (lane & 3) * 2;
    const __half* Bx = Ws + (wn * 32 + (lane >> 2)) * LDh + (lane & 3) * 2;

    #pragma unroll
    for (int kt = 0; kt < FIN / 16; kt++) {
        const int k0 = kt * 16;
        uint4 a0, a1;
        a0.x = *(const uint32_t*)(Ax + k0);
        a0.y = *(const uint32_t*)(Ax + 8 * LDh + k0);
        a0.z = *(const uint32_t*)(Ax + k0 + 8);
        a0.w = *(const uint32_t*)(Ax + 8 * LDh + k0 + 8);
        a1.x = *(const uint32_t*)(Ax + 16 * LDh + k0);
        a1.y = *(const uint32_t*)(Ax + 24 * LDh + k0);
        a1.z = *(const uint32_t*)(Ax + 16 * LDh + k0 + 8);
        a1.w = *(const uint32_t*)(Ax + 24 * LDh + k0 + 8);
        uint32_t b[4][2];
        #pragma unroll
        for (int nt = 0; nt < 4; nt++) {
            b[nt][0] = *(const uint32_t*)(Bx + nt * 8 * LDh + k0);
            b[nt][1] = *(const uint32_t*)(Bx + nt * 8 * LDh + k0 + 8);
        }
        #pragma unroll
        for (int nt = 0; nt < 4; nt++) {
            mma16(acc[0][nt], a0, b[nt][0], b[nt][1]);
            mma16(acc[1][nt], a1, b[nt][0], b[nt][1]);
        }
    }
}

// ---------------- strips/corner: 497 units, 1 per block ----------------
template <int FIN>
__global__ void __launch_bounds__(256) strips_mc(
    const __half* __restrict__ Xt, const __half* __restrict__ MRST,
    const __half* __restrict__ MCST, const __half* __restrict__ MWT,
    float* __restrict__ G, float* __restrict__ CG, float* __restrict__ H)
{
    extern __shared__ __half smh[];
    int u = blockIdx.x;
    size_t ss = (size_t)FIN * FOUT;
    const __half* X; const __half* W; float* dst;
    if (u < 224) {
        int a = u >> 5, Y = u & 31;
        int q = Y > 24 ? Y - 24 : 0;
        X = Xt + (size_t)((a + 24) * S + Y) * 64 * FIN;
        W = MRST + (size_t)(a * 8 + q) * ss;
        dst = G + (size_t)u * 64 * FOUT;
    } else if (u < 448) {
        int t = u - 224;
        int b = t >> 5, Xc = t & 31;
        int p = Xc > 24 ? Xc - 24 : 0;
        X = Xt + (size_t)(Xc * S + b + 24) * 64 * FIN;
        W = MCST + (size_t)(p * 8 + b) * ss;
        dst = CG + (size_t)t * 64 * FOUT;
    } else {
        int t = u - 448;
        int a = t / 7, b = t % 7;
        X = Xt + (size_t)((a + 24) * S + b + 24) * 64 * FIN;
        W = MWT + (size_t)(a * 8 + b) * ss;
        dst = H + (size_t)t * 64 * FOUT;
    }

    float acc[2][4][4] = {};
    unit_gemm<FIN>(X, W, smh, acc);

    int lane = threadIdx.x & 31, wid = threadIdx.x >> 5;
    int wm = wid >> 2, wn = wid & 3;
    int r0 = wm * 32 + (lane >> 2);
    #pragma unroll
    for (int mt = 0; mt < 2; mt++)
        #pragma unroll
        for (int nt = 0; nt < 4; nt++) {
            int g = wn * 32 + nt * 8 + (lane & 3) * 2;
            int r = r0 + mt * 16;
            *(float2*)(dst + r * FOUT + g)       = make_float2(acc[mt][nt][0], acc[mt][nt][1]);
            *(float2*)(dst + (r + 8) * FOUT + g) = make_float2(acc[mt][nt][2], acc[mt][nt][3]);
        }
}

// ---------------- merged prefix pass: rows(G) + rows(CG) + 2-D(H) ----------
__global__ void prefix_all_k(float* __restrict__ G, float* __restrict__ CG,
                             float* __restrict__ H)
{
    int bid = blockIdx.x;
    if (bid < 2048) {
        int t = bid * 256 + threadIdx.x;
        float* buf = (t < 32 * 8192) ? G : CG;
        int tt = t & (32 * 8192 - 1);
        int yy = tt >> 13, mg = tt & 8191;
        float run = 0.f;
        #pragma unroll
        for (int a = 0; a < 7; a++) {
            int idx = (a * 32 + yy) * 8192 + mg;
            run += buf[idx];
            buf[idx] = run;
        }
    } else {
        int mg = (bid - 2048) * 256 + threadIdx.x;
        float colA[7];
        #pragma unroll
        for (int b = 0; b < 7; b++) colA[b] = 0.f;
        #pragma unroll
        for (int a = 0; a < 7; a++) {
            float run = 0.f;
            #pragma unroll
            for (int b = 0; b < 7; b++) {
                int idx = (a * 7 + b) * 8192 + mg;
                run += H[idx];
                colA[b] += run;
                H[idx] = colA[b];
            }
        }
    }
}

// ---------------- combine: 1024 pixels, 1 per block ----------------
template <int FIN, bool OUT_HALF>
__global__ void __launch_bounds__(256) combine_mc(
    const __half* __restrict__ Xt, const __half* __restrict__ WCT,
    const float* __restrict__ Gc, const float* __restrict__ CGc,
    const float* __restrict__ Hc, const float* __restrict__ mb,
    const float* __restrict__ jb, void* __restrict__ Yout)
{
    extern __shared__ __half smh[];
    int p = blockIdx.x;
    int X = p >> 5, Y = p & 31;
    int cx = X <= 24 ? (X < 7 ? X : 7) : X - 17;
    int cy = Y <= 24 ? (Y < 7 ? Y : 7) : Y - 17;
    size_t ss = (size_t)FIN * FOUT;

    float acc[2][4][4] = {};
    unit_gemm<FIN>(Xt + (size_t)p * 64 * FIN,
                   WCT + (size_t)(cx * 15 + cy) * ss, smh, acc);

    const float ms = 1.0f - ALPHA;
    const float* Gp = (X >= 25) ? Gc + (size_t)((X - 25) * S + Y) * 64 * FOUT : 0;
    const float* Cp = (Y >= 25) ? CGc + (size_t)((Y - 25) * S + X) * 64 * FOUT : 0;
    const float* Hp = (X >= 25 && Y >= 25)
        ? Hc + (size_t)((X - 25) * 7 + (Y - 25)) * 64 * FOUT : 0;

    int lane = threadIdx.x & 31, wid = threadIdx.x >> 5;
    int wm = wid >> 2, wn = wid & 3;
    int r0 = wm * 32 + (lane >> 2);

    #pragma unroll
    for (int nt = 0; nt < 4; nt++) {
        int g = wn * 32 + nt * 8 + (lane & 3) * 2;
        float2 bias = make_float2(ms * mb[g]     + ALPHA * jb[g],
                                  ms * mb[g + 1] + ALPHA * jb[g + 1]);
        #pragma unroll
        for (int mt = 0; mt < 2; mt++) {
            #pragma unroll
            for (int half = 0; half < 2; half++) {
                int r = r0 + mt * 16 + half * 8;
                float v0 = acc[mt][nt][half * 2], v1 = acc[mt][nt][half * 2 + 1];
                if (Gp) {
                    float2 s2 = *(const float2*)(Gp + r * FOUT + g);
                    v0 += ms * s2.x; v1 += ms * s2.y;
                }
                if (Cp) {
                    float2 s2 = *(const float2*)(Cp + r * FOUT + g);
                    v0 += ms * s2.x; v1 += ms * s2.y;
                }
                if (Hp) {
                    float2 s2 = *(const float2*)(Hp + r * FOUT + g);
                    v0 += ms * s2.x; v1 += ms * s2.y;
                }
                v0 += bias.x; v1 += bias.y;
                v0 = fmaxf(v0, SLOPE * v0);
                v1 = fmaxf(v1, SLOPE * v1);
                if (OUT_HALF) {
                    __half* O = (__half*)Yout + (size_t)p * 64 * FOUT;
                    *(uint32_t*)(O + r * FOUT + g) = pack_f16x2(v0, v1);
                } else {
                    float* O = (float*)Yout + (size_t)p * 64 * FOUT;
                    *(float2*)(O + r * FOUT + g) = make_float2(v0, v1);
                }
            }
        }
    }
}

// ---------------- host launch ----------------
extern "C" void kernel_launch(void* const* d_in, const int* in_sizes, int n_in,
                              void* d_out, int out_size)
{
    const float* x   = (const float*)d_in[0];
    const float* mw0 = (const float*)d_in[5];
    const float* mb0 = (const float*)d_in[6];
    const float* jw0 = (const float*)d_in[7];
    const float* jb0 = (const float*)d_in[8];
    const float* mw1 = (const float*)d_in[9];
    const float* mb1 = (const float*)d_in[10];
    const float* jw1 = (const float*)d_in[11];
    const float* jb1 = (const float*)d_in[12];
    float* out = (float*)d_out;

    __half *Xt0h, *Yth, *WCT, *MRST, *MCST, *MWT;
    float *Yt2, *G, *CG, *H;
    cudaGetSymbolAddress((void**)&Xt0h, d_Xt0h);
    cudaGetSymbolAddress((void**)&Yth,  d_Yth);
    cudaGetSymbolAddress((void**)&Yt2,  d_Yt2);
    cudaGetSymbolAddress((void**)&WCT,  d_WCT);
    cudaGetSymbolAddress((void**)&MRST, d_MRST);
    cudaGetSymbolAddress((void**)&MCST, d_MCST);
    cudaGetSymbolAddress((void**)&MWT,  d_MWT);
    cudaGetSymbolAddress((void**)&G,    d_G);
    cudaGetSymbolAddress((void**)&CG,   d_CG);
    cudaGetSymbolAddress((void**)&H,    d_H);

    const int smem64  = 192 * (64 + 8)  * 2;   // 27648 B
    const int smem128 = 192 * (128 + 8) * 2;   // 52224 B
    cudaFuncSetAttribute(strips_mc<64>,  cudaFuncAttributeMaxDynamicSharedMemorySize, smem64);
    cudaFuncSetAttribute(combine_mc<64, true>,
                         cudaFuncAttributeMaxDynamicSharedMemorySize, smem64);
    cudaFuncSetAttribute(strips_mc<128>, cudaFuncAttributeMaxDynamicSharedMemorySize, smem128);
    cudaFuncSetAttribute(combine_mc<128, false>,
                         cudaFuncAttributeMaxDynamicSharedMemorySize, smem128);

    dim3 tb(32, 8);
    // x [4096][1024] fp32 -> Xt0h [1024][4096] fp16
    transpose_h_k<<<dim3(1024 / 32, 4096 / 32), tb>>>(Xt0h, x, 4096, 1024);

    // ---- layer 0: Fin = 64 ----
    prep_k<<<dim3((64 * 128) / 256, 4), 256>>>(mw0, jw0, WCT, MRST, MCST, MWT, 64);
    strips_mc<64><<<497, 256, smem64>>>(Xt0h, MRST, MCST, MWT, G, CG, H);
    prefix_all_k<<<2080, 256>>>(G, CG, H);
    combine_mc<64, true><<<1024, 256, smem64>>>(Xt0h, WCT, G, CG, H, mb0, jb0, Yth);

    // ---- layer 1: Fin = 128 ----
    prep_k<<<dim3((128 * 128) / 256, 4), 256>>>(mw1, jw1, WCT, MRST, MCST, MWT, 128);
    strips_mc<128><<<497, 256, smem128>>>(Yth, MRST, MCST, MWT, G, CG, H);
    prefix_all_k<<<2080, 256>>>(G, CG, H);
    combine_mc<128, false><<<1024, 256, smem128>>>(Yth, WCT, G, CG, H, mb1, jb1, Yt2);

    // Yt2 [1024][8192] -> out [8192][1024]
    transpose_k<<<dim3(8192 / 32, 1024 / 32), tb>>>(out, Yt2, 1024, 8192);
}